// round 10
// baseline (speedup 1.0000x reference)
#include <cuda_runtime.h>
#include <math.h>

#define BB 256
#define NN 1000
#define DD 256
#define HH 8
#define DHH 32
#define NEG (-1000000000.0f)

// Intermediates (device globals: no allocation allowed)
__device__ float g_q1[BB * DD];  // glimpse_q
__device__ float g_q2[BB * DD];  // head_in

// ---------------------------------------------------------------------------
// Phase 1: step_context = concat(cur, graph_ctx, dyn) @ W_ctx
// grid = (16 batch-groups, 8 col-chunks of 64), block = 256.
// Thread = (batch, col-quad): 4 cols via float4 weight loads straight from
// L1/L2 (all warps read identical addresses -> L1 hits after first warp).
// ---------------------------------------------------------------------------
__global__ void ctx3_kernel(const float* __restrict__ node_emb,
                            const float* __restrict__ graph_ctx,
                            const float* __restrict__ cap,
                            const float* __restrict__ rd,
                            const float* __restrict__ rn,
                            const float* __restrict__ Wc,
                            const int* __restrict__ head) {
    __shared__ float xs[16 * 515];
    int bg = blockIdx.x, cc = blockIdx.y;
    int t = threadIdx.x;
    int j0 = cc * 64, b0 = bg * 16;

    for (int idx = t; idx < 16 * 515; idx += 256) {
        int b = idx / 515, i = idx - b * 515;
        int bA = b0 + b;
        float v;
        if (i < 256) {
            int hd = head[bA];
            v = node_emb[((size_t)bA * NN + hd) * DD + i];
        } else if (i < 512) v = graph_ctx[bA * DD + (i - 256)];
        else v = (i == 512) ? cap[bA] : (i == 513) ? rd[bA] : rn[bA];
        xs[idx] = v;
    }
    __syncthreads();

    int bp = t >> 4, qi = t & 15;          // 16 batches x 16 col-quads
    const float* xA = xs + bp * 515;
    const float4* Wr = (const float4*)Wc + (j0 >> 2) + qi;  // row stride 128 float4
    float4 acc = make_float4(0.f, 0.f, 0.f, 0.f);
#pragma unroll 5
    for (int i = 0; i < 515; i++) {
        float xv = xA[i];
        float4 w = Wr[(size_t)i * 128];
        acc.x = fmaf(xv, w.x, acc.x);
        acc.y = fmaf(xv, w.y, acc.y);
        acc.z = fmaf(xv, w.z, acc.z);
        acc.w = fmaf(xv, w.w, acc.w);
    }
    int j = j0 + qi * 4;
    int bA = b0 + bp;
    if (j < 256) *(float4*)(g_q1 + bA * DD + j) = acc;
    else         *(float4*)(g_q2 + bA * DD + (j - 256)) = acc;
}

// ---------------------------------------------------------------------------
// Mega kernel: per-batch fused feas + dual-query MHA (8 heads) + proj + logits
// grid = B, block = 1024, dynamic smem 70800 B, 2 blocks/SM.
// ---------------------------------------------------------------------------
__global__ __launch_bounds__(1024, 2)
void mega_kernel(const float* __restrict__ K,
                 const float* __restrict__ V,
                 const float* __restrict__ LK,
                 const float* __restrict__ Wout,
                 const float* __restrict__ Wsa,
                 const int* __restrict__ feasible,
                 float* __restrict__ out_logp,
                 float* __restrict__ out_head) {
    extern __shared__ float sm[];
    float* ps    = sm;            // 16000: interleaved (p1,p2); reused later
    float* q1s   = sm + 16000;    // 256
    float* q2s   = sm + 16256;    // 256
    float* att1s = sm + 16512;    // 256
    float* att2s = sm + 16768;    // 256
    float* gls   = sm + 17024;    // 256
    float* red1  = sm + 17280;    // 32
    float* red2  = sm + 17312;    // 32
    float* redz1 = sm + 17344;    // 32
    float* redz2 = sm + 17376;    // 32
    float* bc    = sm + 17408;    // 4
    int*   ired  = (int*)(sm + 17412);                  // 32 ints
    unsigned char* feas = (unsigned char*)(sm + 17444); // 1024 B
    // total = (17444 + 256) * 4 = 70800 bytes

    int b = blockIdx.x;
    int t = threadIdx.x;
    int warp = t >> 5, lane = t & 31;

    // ---- load queries + feasibility ----
    if (t < DD) { q1s[t] = g_q1[b * DD + t]; q2s[t] = g_q2[b * DD + t]; }
    int f = 0;
    if (t < NN) { f = (feasible[b * NN + t] != 0); feas[t] = (unsigned char)f; }
    else feas[t] = 0;
    int any = __any_sync(0xffffffffu, f);
    if (lane == 0) ired[warp] = any;
    __syncthreads();
    if (t == 0) {
        int a = 0;
#pragma unroll
        for (int i = 0; i < 32; i++) a |= ired[i];
        if (!a) feas[0] = 1;
    }
    __syncthreads();

    // ---- K scores: coalesced, warp covers 4 rows per LDG.128 ----
    int h = warp >> 2, w4 = warp & 3;
    int ch = lane & 7, rsub = lane >> 3;
    const float4* Kb = (const float4*)(K + (size_t)(b * HH + h) * NN * DHH);
    float4 qa = ((const float4*)(q1s + h * DHH))[ch];
    float4 qb = ((const float4*)(q2s + h * DHH))[ch];
    const float scale = 0.17677669529663687f; // 1/sqrt(32)
    float m1l = NEG, m2l = NEG;
    int nbase = w4 * 4 + rsub;
    float2* ps2 = (float2*)ps;
#pragma unroll 2
    for (int i = 0; i < 62; i++) {
        int n = nbase + i * 16;
        float4 kv = Kb[n * 8 + ch];
        float d1 = fmaf(kv.x, qa.x, fmaf(kv.y, qa.y, fmaf(kv.z, qa.z, kv.w * qa.w)));
        float d2 = fmaf(kv.x, qb.x, fmaf(kv.y, qb.y, fmaf(kv.z, qb.z, kv.w * qb.w)));
#pragma unroll
        for (int o = 4; o; o >>= 1) {
            d1 += __shfl_xor_sync(0xffffffffu, d1, o);
            d2 += __shfl_xor_sync(0xffffffffu, d2, o);
        }
        if (ch == 0) {
            bool fe = feas[n] != 0;
            float v1 = fe ? d1 * scale : NEG;
            float v2 = fe ? d2 * scale : NEG;
            ps2[h * NN + n] = make_float2(v1, v2);
            m1l = fmaxf(m1l, v1); m2l = fmaxf(m2l, v2);
        }
    }
    if (w4 < 2) {   // epilogue: rows 992..999 (warp-uniform guard)
        int n = 992 + nbase;
        float4 kv = Kb[n * 8 + ch];
        float d1 = fmaf(kv.x, qa.x, fmaf(kv.y, qa.y, fmaf(kv.z, qa.z, kv.w * qa.w)));
        float d2 = fmaf(kv.x, qb.x, fmaf(kv.y, qb.y, fmaf(kv.z, qb.z, kv.w * qb.w)));
#pragma unroll
        for (int o = 4; o; o >>= 1) {
            d1 += __shfl_xor_sync(0xffffffffu, d1, o);
            d2 += __shfl_xor_sync(0xffffffffu, d2, o);
        }
        if (ch == 0) {
            bool fe = feas[n] != 0;
            float v1 = fe ? d1 * scale : NEG;
            float v2 = fe ? d2 * scale : NEG;
            ps2[h * NN + n] = make_float2(v1, v2);
            m1l = fmaxf(m1l, v1); m2l = fmaxf(m2l, v2);
        }
    }
#pragma unroll
    for (int o = 16; o; o >>= 1) {
        m1l = fmaxf(m1l, __shfl_xor_sync(0xffffffffu, m1l, o));
        m2l = fmaxf(m2l, __shfl_xor_sync(0xffffffffu, m2l, o));
    }
    if (lane == 0) { red1[warp] = m1l; red2[warp] = m2l; }
    __syncthreads();
    float m1 = fmaxf(fmaxf(red1[h * 4], red1[h * 4 + 1]), fmaxf(red1[h * 4 + 2], red1[h * 4 + 3]));
    float m2 = fmaxf(fmaxf(red2[h * 4], red2[h * 4 + 1]), fmaxf(red2[h * 4 + 2], red2[h * 4 + 3]));

    // ---- exp + per-head Z (128 threads per head; each element exp'd once) ----
    int hh = t & 127;
    float z1l = 0.f, z2l = 0.f;
    for (int n = hh; n < NN; n += 128) {
        float2 pv = ps2[h * NN + n];
        float p1 = __expf(pv.x - m1);
        float p2 = __expf(pv.y - m2);
        ps2[h * NN + n] = make_float2(p1, p2);
        z1l += p1; z2l += p2;
    }
#pragma unroll
    for (int o = 16; o; o >>= 1) {
        z1l += __shfl_xor_sync(0xffffffffu, z1l, o);
        z2l += __shfl_xor_sync(0xffffffffu, z2l, o);
    }
    if (lane == 0) { redz1[warp] = z1l; redz2[warp] = z2l; }
    __syncthreads();

    // ---- V pass: 4 warps per head, lane = d, one LDS.64 per n ----
    const float* Vb = V + (size_t)(b * HH + h) * NN * DHH;
    float a1 = 0.f, a2 = 0.f;
#pragma unroll 4
    for (int n = w4; n < NN; n += 4) {
        float2 pv = ps2[h * NN + n];
        float v = Vb[n * DHH + lane];
        a1 = fmaf(pv.x, v, a1);
        a2 = fmaf(pv.y, v, a2);
    }
    __syncthreads();          // all reads of probs done
    ps[t] = a1;               // reuse ps: V partials
    ps[1024 + t] = a2;
    __syncthreads();
    if (t < 512) {
        int q = t >> 8, idx = t & 255;
        int h2 = idx >> 5, d = idx & 31;
        const float* base = ps + q * 1024;
        float sum = base[h2 * 128 + d] + base[h2 * 128 + 32 + d]
                  + base[h2 * 128 + 64 + d] + base[h2 * 128 + 96 + d];
        const float* rz = q ? redz2 : redz1;
        float Z = rz[h2 * 4] + rz[h2 * 4 + 1] + rz[h2 * 4 + 2] + rz[h2 * 4 + 3];
        if (q == 0) att1s[idx] = sum / Z;
        else        att2s[idx] = sum / Z;
    }
    __syncthreads();

    // ---- Wout proj only (all 1024 threads, 4 row-splits of 64) ----
    {
        int split = t >> 8, j = t & 255;
        const float* wp = Wout + (size_t)(split * 64) * DD + j;
        const float* ap = att1s + split * 64;
        float acc = 0.f;
#pragma unroll 8
        for (int i = 0; i < 64; i++) acc = fmaf(ap[i], wp[(size_t)i * DD], acc);
        ps[t] = acc;
        __syncthreads();
        if (t < 256) gls[t] = ps[t] + ps[256 + t] + ps[512 + t] + ps[768 + t];
        __syncthreads();
    }

    // ---- LK logits: coalesced; warp covers 2 rows/iter ----
    int rhalf = lane >> 4;
    int csel = lane & 15;
    const float4* gv = (const float4*)gls;
    for (int k = 0; k < 16; k++) {
        int n = warp * 2 + k * 64 + rhalf;
        float d = 0.f;
        if (n < NN) {
            const float4* r = (const float4*)(LK + ((size_t)b * NN + n) * DD);
#pragma unroll
            for (int jj = 0; jj < 4; jj++) {
                float4 kv = r[csel + jj * 16];
                float4 g = gv[csel + jj * 16];
                d = fmaf(kv.x, g.x, d); d = fmaf(kv.y, g.y, d);
                d = fmaf(kv.z, g.z, d); d = fmaf(kv.w, g.w, d);
            }
        }
#pragma unroll
        for (int o = 8; o; o >>= 1) d += __shfl_xor_sync(0xffffffffu, d, o);
        if (csel == 0 && n < NN) {
            float lg = 10.0f * tanhf(d * 0.0625f);
            ps[n] = feas[n] ? lg : NEG;   // reuse ps[0..999]: logits
        }
    }
    __syncthreads();

    // ---- log-softmax ----
    float l = (t < NN) ? ps[t] : NEG;
    float v = l;
#pragma unroll
    for (int o = 16; o; o >>= 1) v = fmaxf(v, __shfl_xor_sync(0xffffffffu, v, o));
    if (lane == 0) red1[warp] = v;
    __syncthreads();
    if (t < 32) {
        float x = red1[t];
#pragma unroll
        for (int o = 16; o; o >>= 1) x = fmaxf(x, __shfl_xor_sync(0xffffffffu, x, o));
        if (t == 0) bc[0] = x;
    }
    __syncthreads();
    float m = bc[0];
    float e = (t < NN) ? __expf(l - m) : 0.f;
#pragma unroll
    for (int o = 16; o; o >>= 1) e += __shfl_xor_sync(0xffffffffu, e, o);
    if (lane == 0) red2[warp] = e;
    __syncthreads();
    if (t < 32) {
        float x = red2[t];
#pragma unroll
        for (int o = 16; o; o >>= 1) x += __shfl_xor_sync(0xffffffffu, x, o);
        if (t == 0) bc[1] = x;
    }
    __syncthreads();
    float lse = m + __logf(bc[1]);
    if (t < NN) out_logp[b * NN + t] = l - lse;

    // ---- deferred Wsa proj + out_head (tail; overlaps other blocks' DRAM) ----
    {
        int split = t >> 8, j = t & 255;
        const float* wp = Wsa + (size_t)(split * 64) * DD + j;
        const float* ap = att2s + split * 64;
        float acc = 0.f;
#pragma unroll 8
        for (int i = 0; i < 64; i++) acc = fmaf(ap[i], wp[(size_t)i * DD], acc);
        __syncthreads();      // ensure log-softmax reads of ps[] are done
        ps[t] = acc;
        __syncthreads();
        if (t < 256) out_head[b * DD + t] = ps[t] + ps[256 + t] + ps[512 + t] + ps[768 + t];
    }
}

// ---------------------------------------------------------------------------
extern "C" void kernel_launch(void* const* d_in, const int* in_sizes, int n_in,
                              void* d_out, int out_size) {
    const float* node_emb  = (const float*)d_in[0];
    const float* graph_ctx = (const float*)d_in[1];
    const float* K         = (const float*)d_in[2];
    const float* V         = (const float*)d_in[3];
    const float* LK        = (const float*)d_in[4];
    const float* cap       = (const float*)d_in[5];
    const float* rd        = (const float*)d_in[6];
    const float* rn        = (const float*)d_in[7];
    const float* Wc        = (const float*)d_in[8];
    const float* Wout      = (const float*)d_in[9];
    const float* Wsa       = (const float*)d_in[10];
    const int*   head      = (const int*)d_in[11];
    const int*   feasible  = (const int*)d_in[12];
    float* out = (float*)d_out;

    static bool attr_done = false;
    if (!attr_done) {
        cudaFuncSetAttribute(mega_kernel, cudaFuncAttributeMaxDynamicSharedMemorySize, 70912);
        attr_done = true;
    }

    ctx3_kernel<<<dim3(16, 8), 256>>>(node_emb, graph_ctx, cap, rd, rn, Wc, head);
    mega_kernel<<<BB, 1024, 70800>>>(K, V, LK, Wout, Wsa, feasible, out, out + BB * NN);
}

// round 11
// speedup vs baseline: 1.8160x; 1.8160x over previous
#include <cuda_runtime.h>
#include <math.h>

#define BB 256
#define NN 1000
#define DD 256
#define HH 8
#define DHH 32
#define NEG (-1000000000.0f)

// ---------------------------------------------------------------------------
// Single mega kernel: per-batch ctx-GEMM + feas + dual-query MHA (8 heads)
// + proj + logits + log-softmax.
// grid = B, block = 1024, dynamic smem 70800 B, 2 blocks/SM.
// ---------------------------------------------------------------------------
__global__ __launch_bounds__(1024, 2)
void mega_kernel(const float* __restrict__ node_emb,
                 const float* __restrict__ graph_ctx,
                 const float* __restrict__ K,
                 const float* __restrict__ V,
                 const float* __restrict__ LK,
                 const float* __restrict__ cap,
                 const float* __restrict__ rd,
                 const float* __restrict__ rn,
                 const float* __restrict__ Wc,
                 const float* __restrict__ Wout,
                 const float* __restrict__ Wsa,
                 const int* __restrict__ head,
                 const int* __restrict__ feasible,
                 float* __restrict__ out_logp,
                 float* __restrict__ out_head) {
    extern __shared__ float sm[];
    float* ps    = sm;            // 16000: x | ctx partials | probs | scratch
    float* q1s   = sm + 16000;    // 256
    float* q2s   = sm + 16256;    // 256
    float* att1s = sm + 16512;    // 256
    float* att2s = sm + 16768;    // 256
    float* gls   = sm + 17024;    // 256
    float* red1  = sm + 17280;    // 32
    float* red2  = sm + 17312;    // 32
    float* redz1 = sm + 17344;    // 32
    float* redz2 = sm + 17376;    // 32
    float* bc    = sm + 17408;    // 4
    int*   ired  = (int*)(sm + 17412);                  // 32 ints
    unsigned char* feas = (unsigned char*)(sm + 17444); // 1024 B
    // total = (17444 + 256) * 4 = 70800 bytes

    int b = blockIdx.x;
    int t = threadIdx.x;
    int warp = t >> 5, lane = t & 31;

    // ================= Phase 0: stage x + feasibility =================
    // x = concat(node_emb[b, head[b]], graph_ctx[b], [cap, rd, rn])  (515)
    if (t < 515) {
        float v;
        if (t < 256) {
            int hd = head[b];
            v = node_emb[((size_t)b * NN + hd) * DD + t];
        } else if (t < 512) v = graph_ctx[b * DD + (t - 256)];
        else v = (t == 512) ? cap[b] : (t == 513) ? rd[b] : rn[b];
        ps[t] = v;
    }
    int f = 0;
    if (t < NN) { f = (feasible[b * NN + t] != 0); feas[t] = (unsigned char)f; }
    else feas[t] = 0;
    int any = __any_sync(0xffffffffu, f);
    if (lane == 0) ired[warp] = any;
    __syncthreads();
    if (t == 0) {
        int a = 0;
#pragma unroll
        for (int i = 0; i < 32; i++) a |= ired[i];
        if (!a) feas[0] = 1;
    }

    // ================= Phase 1: ctx GEMM  q = x @ Wc  =================
    // thread t: col j = t&511, i-half = t>>9. W coalesced across lanes;
    // W_ctx (1MB) is L2-resident across the grid.
    {
        int j = t & 511, half = t >> 9;
        int i0 = half ? 258 : 0;
        int i1 = half ? 515 : 258;
        float acc = 0.f;
        const float* wp = Wc + (size_t)i0 * 512 + j;
#pragma unroll 8
        for (int i = i0; i < i1; i++, wp += 512)
            acc = fmaf(ps[i], *wp, acc);
        __syncthreads();                 // x reads done before partial store
        ps[515 + half * 512 + j] = acc;
    }
    __syncthreads();
    if (t < 512) {
        float q = ps[515 + t] + ps[1027 + t];
        if (t < 256) q1s[t] = q;
        else         q2s[t - 256] = q;
    }
    __syncthreads();

    // ================= Phase 2: K scores (coalesced) =================
    int h = warp >> 2, w4 = warp & 3;
    int ch = lane & 7, rsub = lane >> 3;
    const float4* Kb = (const float4*)(K + (size_t)(b * HH + h) * NN * DHH);
    float4 qa = ((const float4*)(q1s + h * DHH))[ch];
    float4 qb = ((const float4*)(q2s + h * DHH))[ch];
    const float scale = 0.17677669529663687f; // 1/sqrt(32)
    float m1l = NEG, m2l = NEG;
    int nbase = w4 * 4 + rsub;
    float2* ps2 = (float2*)ps;
#pragma unroll 2
    for (int i = 0; i < 62; i++) {
        int n = nbase + i * 16;
        float4 kv = Kb[n * 8 + ch];
        float d1 = fmaf(kv.x, qa.x, fmaf(kv.y, qa.y, fmaf(kv.z, qa.z, kv.w * qa.w)));
        float d2 = fmaf(kv.x, qb.x, fmaf(kv.y, qb.y, fmaf(kv.z, qb.z, kv.w * qb.w)));
#pragma unroll
        for (int o = 4; o; o >>= 1) {
            d1 += __shfl_xor_sync(0xffffffffu, d1, o);
            d2 += __shfl_xor_sync(0xffffffffu, d2, o);
        }
        if (ch == 0) {
            bool fe = feas[n] != 0;
            float v1 = fe ? d1 * scale : NEG;
            float v2 = fe ? d2 * scale : NEG;
            ps2[h * NN + n] = make_float2(v1, v2);
            m1l = fmaxf(m1l, v1); m2l = fmaxf(m2l, v2);
        }
    }
    if (w4 < 2) {   // rows 992..999 (warp-uniform guard)
        int n = 992 + nbase;
        float4 kv = Kb[n * 8 + ch];
        float d1 = fmaf(kv.x, qa.x, fmaf(kv.y, qa.y, fmaf(kv.z, qa.z, kv.w * qa.w)));
        float d2 = fmaf(kv.x, qb.x, fmaf(kv.y, qb.y, fmaf(kv.z, qb.z, kv.w * qb.w)));
#pragma unroll
        for (int o = 4; o; o >>= 1) {
            d1 += __shfl_xor_sync(0xffffffffu, d1, o);
            d2 += __shfl_xor_sync(0xffffffffu, d2, o);
        }
        if (ch == 0) {
            bool fe = feas[n] != 0;
            float v1 = fe ? d1 * scale : NEG;
            float v2 = fe ? d2 * scale : NEG;
            ps2[h * NN + n] = make_float2(v1, v2);
            m1l = fmaxf(m1l, v1); m2l = fmaxf(m2l, v2);
        }
    }
#pragma unroll
    for (int o = 16; o; o >>= 1) {
        m1l = fmaxf(m1l, __shfl_xor_sync(0xffffffffu, m1l, o));
        m2l = fmaxf(m2l, __shfl_xor_sync(0xffffffffu, m2l, o));
    }
    if (lane == 0) { red1[warp] = m1l; red2[warp] = m2l; }
    __syncthreads();
    float m1 = fmaxf(fmaxf(red1[h * 4], red1[h * 4 + 1]), fmaxf(red1[h * 4 + 2], red1[h * 4 + 3]));
    float m2 = fmaxf(fmaxf(red2[h * 4], red2[h * 4 + 1]), fmaxf(red2[h * 4 + 2], red2[h * 4 + 3]));

    // ================= Phase 3: exp + per-head Z =================
    int hh = t & 127;
    float z1l = 0.f, z2l = 0.f;
    for (int n = hh; n < NN; n += 128) {
        float2 pv = ps2[h * NN + n];
        float p1 = __expf(pv.x - m1);
        float p2 = __expf(pv.y - m2);
        ps2[h * NN + n] = make_float2(p1, p2);
        z1l += p1; z2l += p2;
    }
#pragma unroll
    for (int o = 16; o; o >>= 1) {
        z1l += __shfl_xor_sync(0xffffffffu, z1l, o);
        z2l += __shfl_xor_sync(0xffffffffu, z2l, o);
    }
    if (lane == 0) { redz1[warp] = z1l; redz2[warp] = z2l; }
    __syncthreads();

    // ================= Phase 4: V pass =================
    const float* Vb = V + (size_t)(b * HH + h) * NN * DHH;
    float a1 = 0.f, a2 = 0.f;
#pragma unroll 4
    for (int n = w4; n < NN; n += 4) {
        float2 pv = ps2[h * NN + n];
        float v = Vb[n * DHH + lane];
        a1 = fmaf(pv.x, v, a1);
        a2 = fmaf(pv.y, v, a2);
    }
    __syncthreads();          // all reads of probs done
    ps[t] = a1;               // reuse ps: V partials
    ps[1024 + t] = a2;
    __syncthreads();
    if (t < 512) {
        int q = t >> 8, idx = t & 255;
        int h2 = idx >> 5, d = idx & 31;
        const float* base = ps + q * 1024;
        float sum = base[h2 * 128 + d] + base[h2 * 128 + 32 + d]
                  + base[h2 * 128 + 64 + d] + base[h2 * 128 + 96 + d];
        const float* rz = q ? redz2 : redz1;
        float Z = rz[h2 * 4] + rz[h2 * 4 + 1] + rz[h2 * 4 + 2] + rz[h2 * 4 + 3];
        if (q == 0) att1s[idx] = sum / Z;
        else        att2s[idx] = sum / Z;
    }
    __syncthreads();

    // ================= Phase 5: Wout proj (1024 threads) =================
    {
        int split = t >> 8, j = t & 255;
        const float* wp = Wout + (size_t)(split * 64) * DD + j;
        const float* ap = att1s + split * 64;
        float acc = 0.f;
#pragma unroll 8
        for (int i = 0; i < 64; i++) acc = fmaf(ap[i], wp[(size_t)i * DD], acc);
        ps[t] = acc;
        __syncthreads();
        if (t < 256) gls[t] = ps[t] + ps[256 + t] + ps[512 + t] + ps[768 + t];
        __syncthreads();
    }

    // ================= Phase 6: LK logits (coalesced) =================
    int rhalf = lane >> 4;
    int csel = lane & 15;
    const float4* gv = (const float4*)gls;
    for (int k = 0; k < 16; k++) {
        int n = warp * 2 + k * 64 + rhalf;
        float d = 0.f;
        if (n < NN) {
            const float4* r = (const float4*)(LK + ((size_t)b * NN + n) * DD);
#pragma unroll
            for (int jj = 0; jj < 4; jj++) {
                float4 kv = r[csel + jj * 16];
                float4 g = gv[csel + jj * 16];
                d = fmaf(kv.x, g.x, d); d = fmaf(kv.y, g.y, d);
                d = fmaf(kv.z, g.z, d); d = fmaf(kv.w, g.w, d);
            }
        }
#pragma unroll
        for (int o = 8; o; o >>= 1) d += __shfl_xor_sync(0xffffffffu, d, o);
        if (csel == 0 && n < NN) {
            float lg = 10.0f * tanhf(d * 0.0625f);
            ps[n] = feas[n] ? lg : NEG;   // reuse ps[0..999]: logits
        }
    }
    __syncthreads();

    // ================= Phase 7: log-softmax =================
    float l = (t < NN) ? ps[t] : NEG;
    float v = l;
#pragma unroll
    for (int o = 16; o; o >>= 1) v = fmaxf(v, __shfl_xor_sync(0xffffffffu, v, o));
    if (lane == 0) red1[warp] = v;
    __syncthreads();
    if (t < 32) {
        float x = red1[t];
#pragma unroll
        for (int o = 16; o; o >>= 1) x = fmaxf(x, __shfl_xor_sync(0xffffffffu, x, o));
        if (t == 0) bc[0] = x;
    }
    __syncthreads();
    float m = bc[0];
    float e = (t < NN) ? __expf(l - m) : 0.f;
#pragma unroll
    for (int o = 16; o; o >>= 1) e += __shfl_xor_sync(0xffffffffu, e, o);
    if (lane == 0) red2[warp] = e;
    __syncthreads();
    if (t < 32) {
        float x = red2[t];
#pragma unroll
        for (int o = 16; o; o >>= 1) x += __shfl_xor_sync(0xffffffffu, x, o);
        if (t == 0) bc[1] = x;
    }
    __syncthreads();
    float lse = m + __logf(bc[1]);
    if (t < NN) out_logp[b * NN + t] = l - lse;

    // ====== Phase 8: deferred Wsa proj + out_head (tail, overlaps) ======
    {
        int split = t >> 8, j = t & 255;
        const float* wp = Wsa + (size_t)(split * 64) * DD + j;
        const float* ap = att2s + split * 64;
        float acc = 0.f;
#pragma unroll 8
        for (int i = 0; i < 64; i++) acc = fmaf(ap[i], wp[(size_t)i * DD], acc);
        __syncthreads();      // log-softmax reads of ps[] done
        ps[t] = acc;
        __syncthreads();
        if (t < 256) out_head[b * DD + t] = ps[t] + ps[256 + t] + ps[512 + t] + ps[768 + t];
    }
}

// ---------------------------------------------------------------------------
extern "C" void kernel_launch(void* const* d_in, const int* in_sizes, int n_in,
                              void* d_out, int out_size) {
    const float* node_emb  = (const float*)d_in[0];
    const float* graph_ctx = (const float*)d_in[1];
    const float* K         = (const float*)d_in[2];
    const float* V         = (const float*)d_in[3];
    const float* LK        = (const float*)d_in[4];
    const float* cap       = (const float*)d_in[5];
    const float* rd        = (const float*)d_in[6];
    const float* rn        = (const float*)d_in[7];
    const float* Wc        = (const float*)d_in[8];
    const float* Wout      = (const float*)d_in[9];
    const float* Wsa       = (const float*)d_in[10];
    const int*   head      = (const int*)d_in[11];
    const int*   feasible  = (const int*)d_in[12];
    float* out = (float*)d_out;

    static bool attr_done = false;
    if (!attr_done) {
        cudaFuncSetAttribute(mega_kernel, cudaFuncAttributeMaxDynamicSharedMemorySize, 70912);
        attr_done = true;
    }

    mega_kernel<<<BB, 1024, 70800>>>(node_emb, graph_ctx, K, V, LK, cap, rd, rn,
                                     Wc, Wout, Wsa, head, feasible,
                                     out, out + BB * NN);
}